// round 11
// baseline (speedup 1.0000x reference)
#include <cuda_runtime.h>

#define HH 512
#define WW 512
#define TBINS 180
#define RBINS 360
#define NPIX (HH*WW)
#define TT 20                 // theta bins per vote tile
#define NTILE (TBINS/TT)      // 9
#define NSPLIT 116            // pixel splits in vote (9*116 = 1044 blocks, ~7/SM)
#define CDF_BLOCKS 2048       // 16384 warps

// scratch (no cudaMalloc allowed)
static __device__ float4 g_pts[NPIX];       // theta, rho, sig_t, sig_r
static __device__ float  g_val[NPIX];       // mask value of valid pixel
static __device__ int    g_count;
static __device__ float  g_wt[NPIX * 180];  // dense theta weights per valid pixel
static __device__ float  g_wr[NPIX * 32];   // sparse rho weights (zero-padded to 32)
static __device__ int    g_meta[NPIX];      // rho: lo_b | (cnt<<16)

// bin-edge constants
#define TMIN_D (-1.5707963267948966)
#define TBIN_D (3.14159265358979323846 / 179.0)
#define RMAX_D 724.07734393502470        /* sqrt(512^2+512^2) */
#define RBIN_D (2.0 * RMAX_D / 359.0)
#define TMIN_F ((float)TMIN_D)
#define TBIN_F ((float)TBIN_D)
#define RMIN_F ((float)(-RMAX_D))
#define RBIN_F ((float)RBIN_D)

// fast normal CDF: pure-polynomial erff path (no erfcf/exp).
__device__ __forceinline__ float fcdf(float x) {
    return 0.5f * (1.0f + erff(x * 0.7071067811865476f));
}

// Per-pixel plane fit body: bit-exact reference fp32 arithmetic.
// Returns valid flag; outputs pt/val.
__device__ __forceinline__ bool plane_fit(const float* __restrict__ img,
                                          const float* __restrict__ mask,
                                          int h, int w, float4& pt, float& val) {
    int hm = max(h - 1, 0), hp = min(h + 1, HH - 1);
    int wm = max(w - 1, 0), wp = min(w + 1, WW - 1);
    const float* r0 = img + hm * WW;
    const float* r1 = img + h  * WW;
    const float* r2 = img + hp * WW;
    float a00 = r0[wm], a01 = r0[w], a02 = r0[wp];
    float a10 = r1[wm], a11 = r1[w], a12 = r1[wp];
    float a20 = r2[wm], a21 = r2[w], a22 = r2[wp];

    float asum = __fadd_rn(__fadd_rn(__fadd_rn(__fadd_rn(__fadd_rn(
                 -a00, -a01), -a02), a20), a21), a22);
    float bsum = __fadd_rn(__fadd_rn(__fadd_rn(__fadd_rn(__fadd_rn(
                 -a00, a02), -a10), a12), -a20), a22);
    float gsum = __fadd_rn(__fadd_rn(__fadd_rn(__fadd_rn(__fadd_rn(__fadd_rn(
                 __fadd_rn(__fadd_rn(a00, a01), a02), a10), a11), a12), a20), a21), a22);

    float alpha = __fadd_rn(__fdiv_rn(asum, 6.0f), 1e-6f);
    float beta  = __fadd_rn(__fdiv_rn(bsum, 6.0f), 1e-6f);
    float gamma = __fdiv_rn(gsum, 9.0f);

    float rs_arr[3] = { a01, a11, a21 };
    float bd_arr[3] = { -beta, 0.0f, beta };
    float ad_arr[3] = { -alpha, 0.0f, alpha };
    float eps2 = 0.0f;
#pragma unroll
    for (int i = 0; i < 3; i++) {
#pragma unroll
        for (int j = 0; j < 3; j++) {
            float r = __fsub_rn(__fsub_rn(__fsub_rn(rs_arr[i], ad_arr[j]), bd_arr[i]), gamma);
            eps2 = __fadd_rn(eps2, __fmul_rn(r, r));
        }
    }
    float nv = __fdiv_rn(eps2, 7.0f);
    float va = __fdiv_rn(nv, 6.0f);

    float aa = __fmul_rn(alpha, alpha);
    float bb = __fmul_rn(beta, beta);
    float g2 = __fadd_rn(aa, bb);
    float num = __fadd_rn(__fmul_rn(bb, va), __fmul_rn(aa, va));
    float var_t = __fdiv_rn(num, __fmul_rn(g2, g2));

    float theta = atanf(__fdiv_rn(beta, alpha));
    // cos/sin of atan(b/a) via rsqrt (validated R9/R10)
    float inv = rsqrtf(g2);
    float invs = copysignf(inv, alpha);
    float ct = alpha * invs;
    float st = beta  * invs;
    float xf = (float)h, yf = (float)w;
    float rho  = __fadd_rn(__fmul_rn(xf, ct), __fmul_rn(yf, st));
    float drho = __fadd_rn(__fmul_rn(-xf, st), __fmul_rn(yf, ct));
    float var_r = __fmul_rn(__fmul_rn(drho, drho), var_t);

    float v = mask[h * WW + w];
    pt = make_float4(theta, rho,
                     __fsqrt_rn(__fadd_rn(var_t, 1e-12f)),
                     __fsqrt_rn(__fadd_rn(var_r, 1e-12f)));
    val = v;
    return (var_t <= 100.0f) && (var_r <= 100.0f) && (v != 0.0f);
}

__device__ __forceinline__ void compact_emit(bool valid, const float4& pt,
                                             float v, int lane) {
    unsigned m = __ballot_sync(0xffffffffu, valid);
    if (m) {
        int leader = __ffs(m) - 1;
        int base = 0;
        if (lane == leader) base = atomicAdd(&g_count, __popc(m));
        base = __shfl_sync(0xffffffffu, base, leader);
        if (valid) {
            int idx = base + __popc(m & ((1u << lane) - 1u));
            g_pts[idx] = pt;
            g_val[idx] = v;
        }
    }
}

// Two pixels per thread (vertical pair h, h+8): two independent latency
// chains -> ~2x ILP at same occupancy. Also zeroes d_out.
__global__ void __launch_bounds__(256)
plane_kernel(const float* __restrict__ img,
             const float* __restrict__ mask,
             float* __restrict__ out) {
    int bid = blockIdx.y * (WW / 32) + blockIdx.x;
    int tid = threadIdx.y * 32 + threadIdx.x;
    int zi = bid * 256 + tid;
    if (zi < (TBINS * RBINS) / 4)
        ((float4*)out)[zi] = make_float4(0.f, 0.f, 0.f, 0.f);
    int zi2 = (512 + bid) * 256 + tid;
    if (zi2 < (TBINS * RBINS) / 4)
        ((float4*)out)[zi2] = make_float4(0.f, 0.f, 0.f, 0.f);

    int w  = blockIdx.x * 32 + threadIdx.x;
    int h0 = blockIdx.y * 16 + threadIdx.y;
    int h1 = h0 + 8;

    float4 pt0, pt1; float v0, v1;
    bool ok0 = plane_fit(img, mask, h0, w, pt0, v0);
    bool ok1 = plane_fit(img, mask, h1, w, pt1, v1);

    int lane = threadIdx.x;
    compact_emit(ok0, pt0, v0, lane);
    compact_emit(ok1, pt1, v1, lane);
}

// One warp per valid pixel (grid-stride, load-balanced): windowed theta-edge
// CDFs (dense wt[180]) + windowed rho-edge CDFs (sparse wr, <=32 bins).
__global__ void __launch_bounds__(256)
cdf_kernel() {
    __shared__ float tbuf[8][184];
    int lane = threadIdx.x & 31;
    int wl   = threadIdx.x >> 5;
    int warp = blockIdx.x * 8 + wl;
    int n = g_count;

    for (int p = warp; p < n; p += CDF_BLOCKS * 8) {
        float4 pt = g_pts[p];
        float theta = pt.x, rho = pt.y, sig_t = pt.z, sig_r = pt.w;
        float rst = __fdiv_rn(1.0f, sig_t);
        float rsr = __fdiv_rn(1.0f, sig_r);

        // theta: window of non-saturated edges
        float Wt = 6.5f * sig_t;
        int klo = max(0,   (int)ceilf ((theta - Wt - TMIN_F) / TBIN_F + 0.5f));
        int khi = min(180, (int)floorf((theta + Wt - TMIN_F) / TBIN_F + 0.5f));
        klo = min(klo, 181);
        for (int e = klo + lane; e <= khi; e += 32) {
            float ec = __fadd_rn(TMIN_F, __fmul_rn(__fsub_rn((float)e, 0.5f), TBIN_F));
            tbuf[wl][e - klo] = fcdf((ec - theta) * rst);
        }
        __syncwarp();
        float* wtp = g_wt + p * 180;
        for (int j = lane; j < 180; j += 32) {
            float c0 = (j     < klo) ? 0.0f : ((j     > khi) ? 1.0f : tbuf[wl][j     - klo]);
            float c1 = (j + 1 < klo) ? 0.0f : ((j + 1 > khi) ? 1.0f : tbuf[wl][j + 1 - klo]);
            wtp[j] = __fsub_rn(c1, c0);
        }
        __syncwarp();   // tbuf reuse below

        // rho: window capped so bins <= 32
        float Wr = fminf(6.5f * sig_r, 62.0f);
        int rklo = max(0,   (int)ceilf ((rho - Wr - RMIN_F) / RBIN_F + 0.5f));
        int rkhi = min(360, (int)floorf((rho + Wr - RMIN_F) / RBIN_F + 0.5f));
        rklo = min(rklo, 360);
        int e = rklo + lane;
        if (e <= rkhi) {
            float ec = __fadd_rn(RMIN_F, __fmul_rn(__fsub_rn((float)e, 0.5f), RBIN_F));
            tbuf[wl][lane] = fcdf((ec - rho) * rsr);
        }
        __syncwarp();
        int lo_b = min(max(0, rklo - 1), 359);
        int hi_b = min(359, rkhi);
        int cnt  = min(max(hi_b - lo_b + 1, 1), 32);
        float v = g_val[p];
        float wr = 0.0f;
        int b = lo_b + lane;
        if (lane < cnt) {
            float c0 = (b     < rklo) ? 0.0f : tbuf[wl][b     - rklo];
            float c1 = (b + 1 > rkhi) ? 1.0f : tbuf[wl][b + 1 - rklo];
            wr = __fmul_rn(__fsub_rn(c1, c0), v);
        }
        g_wr[p * 32 + lane] = wr;           // zero-padded to full 32 lanes
        if (lane == 0) g_meta[p] = lo_b | (cnt << 16);
        __syncwarp();
    }
}

// blockIdx.x = theta tile (20 bins), blockIdx.y = pixel split.
// Static smem accumulator 20x360 (28.8KB) -> 7 blocks/SM.
__global__ void __launch_bounds__(256, 7)
vote_kernel(float* __restrict__ out) {
    __shared__ float sacc[TT * RBINS];
    int tid  = threadIdx.x;
    int lane = tid & 31;
    int warp = tid >> 5;
    int tile = blockIdx.x;

    for (int i = tid; i < TT * RBINS; i += 256) sacc[i] = 0.0f;
    __syncthreads();

    int n = g_count;
    const int stride = NSPLIT * 8;

    for (int p = blockIdx.y * 8 + warp; p < n; p += stride) {
        int   meta = g_meta[p];
        float wrv  = g_wr[p * 32 + lane];
        const float4* w4 = (const float4*)(g_wt + p * 180 + tile * TT);

        int base = (meta & 0xffff) + lane;
        if (wrv != 0.0f) {
#pragma unroll
            for (int c = 0; c < TT / 4; c++) {
                float4 wv = w4[c];
                atomicAdd(&sacc[(c * 4 + 0) * RBINS + base], wv.x * wrv);
                atomicAdd(&sacc[(c * 4 + 1) * RBINS + base], wv.y * wrv);
                atomicAdd(&sacc[(c * 4 + 2) * RBINS + base], wv.z * wrv);
                atomicAdd(&sacc[(c * 4 + 3) * RBINS + base], wv.w * wrv);
            }
        }
    }

    __syncthreads();
    // float4 global atomic merge (sm_90+)
    float4* outp = (float4*)(out + tile * TT * RBINS);
    const float4* sp = (const float4*)sacc;
    for (int i = tid; i < (TT * RBINS) / 4; i += 256) {
        float4 v = sp[i];
        if (v.x != 0.0f || v.y != 0.0f || v.z != 0.0f || v.w != 0.0f)
            atomicAdd(&outp[i], v);
    }
}

extern "C" void kernel_launch(void* const* d_in, const int* in_sizes, int n_in,
                              void* d_out, int out_size) {
    const float* img  = (const float*)d_in[0];
    const float* mask = (const float*)d_in[1];
    float* out = (float*)d_out;

    void* cnt_ptr = nullptr;
    cudaGetSymbolAddress(&cnt_ptr, g_count);
    cudaMemsetAsync(cnt_ptr, 0, sizeof(int));

    plane_kernel<<<dim3(WW / 32, HH / 16), dim3(32, 8)>>>(img, mask, out);
    cdf_kernel<<<CDF_BLOCKS, 256>>>();
    vote_kernel<<<dim3(NTILE, NSPLIT), 256>>>(out);
}

// round 13
// speedup vs baseline: 1.1314x; 1.1314x over previous
#include <cuda_runtime.h>
#include <cstdint>

#define HH 512
#define WW 512
#define TBINS 180
#define RBINS 360
#define NPIX (HH*WW)
#define CDF_BLOCKS 2048       // 16384 warps
#define NCG 12                // column groups of 32 buckets
#define NTL 6                 // theta tiles of 30 rows
#define NSP 8                 // pixel splits in vote

// scratch (no cudaMalloc allowed)
static __device__ float4 g_pts[NPIX];       // theta, rho, sig_t, sig_r (raw order)
static __device__ float  g_val[NPIX];       // mask value (raw order)
static __device__ int    g_misc[721];       // [0]=count, [1..360]=bcnt, [361..720]=bfill
static __device__ int    g_boff[361];       // bucket prefix offsets
static __device__ float  g_wt[(size_t)NPIX * 180]; // theta weights, BUCKET order
static __device__ float  g_wr[(size_t)NPIX * 32];  // rho weights (32, zero-pad), BUCKET order

// bin-edge constants
#define TMIN_F (-1.5707963267948966f)
#define TBIN_F ((float)(3.14159265358979323846 / 179.0))
#define RMAX_D 724.07734393502470
#define RMIN_F ((float)(-RMAX_D))
#define RBIN_F ((float)(2.0 * RMAX_D / 359.0))

__device__ __forceinline__ float fcdf(float x) {
    return 0.5f * (1.0f + erff(x * 0.7071067811865476f));
}

// rlo from (rho, sig_r): MUST be identical text in plane and cdf.
__device__ __forceinline__ int calc_rlo(float rho, float sig_r) {
    float Wr = fminf(6.5f * sig_r, 62.0f);
    int rklo = max(0, (int)ceilf((rho - Wr - RMIN_F) / RBIN_F + 0.5f));
    rklo = min(rklo, 360);
    return min(max(0, rklo - 1), 359);
}

// ---------------- plane: fit + validity (bit-exact) + compact + rlo histogram ----------------
__global__ void plane_kernel(const float* __restrict__ img,
                             const float* __restrict__ mask,
                             float* __restrict__ out) {
    int bid = blockIdx.y * (WW / 32) + blockIdx.x;
    int zi = bid * 256 + threadIdx.y * 32 + threadIdx.x;
    if (zi < (TBINS * RBINS) / 4)
        ((float4*)out)[zi] = make_float4(0.f, 0.f, 0.f, 0.f);

    int w = blockIdx.x * 32 + threadIdx.x;
    int h = blockIdx.y * 8  + threadIdx.y;
    int hm = max(h - 1, 0), hp = min(h + 1, HH - 1);
    int wm = max(w - 1, 0), wp = min(w + 1, WW - 1);
    const float* r0 = img + hm * WW;
    const float* r1 = img + h  * WW;
    const float* r2 = img + hp * WW;
    float a00 = r0[wm], a01 = r0[w], a02 = r0[wp];
    float a10 = r1[wm], a11 = r1[w], a12 = r1[wp];
    float a20 = r2[wm], a21 = r2[w], a22 = r2[wp];

    float asum = __fadd_rn(__fadd_rn(__fadd_rn(__fadd_rn(__fadd_rn(
                 -a00, -a01), -a02), a20), a21), a22);
    float bsum = __fadd_rn(__fadd_rn(__fadd_rn(__fadd_rn(__fadd_rn(
                 -a00, a02), -a10), a12), -a20), a22);
    float gsum = __fadd_rn(__fadd_rn(__fadd_rn(__fadd_rn(__fadd_rn(__fadd_rn(
                 __fadd_rn(__fadd_rn(a00, a01), a02), a10), a11), a12), a20), a21), a22);

    float alpha = __fadd_rn(__fdiv_rn(asum, 6.0f), 1e-6f);
    float beta  = __fadd_rn(__fdiv_rn(bsum, 6.0f), 1e-6f);
    float gamma = __fdiv_rn(gsum, 9.0f);

    float rs_arr[3] = { a01, a11, a21 };
    float bd_arr[3] = { -beta, 0.0f, beta };
    float ad_arr[3] = { -alpha, 0.0f, alpha };
    float eps2 = 0.0f;
#pragma unroll
    for (int i = 0; i < 3; i++)
#pragma unroll
        for (int j = 0; j < 3; j++) {
            float r = __fsub_rn(__fsub_rn(__fsub_rn(rs_arr[i], ad_arr[j]), bd_arr[i]), gamma);
            eps2 = __fadd_rn(eps2, __fmul_rn(r, r));
        }
    float nv = __fdiv_rn(eps2, 7.0f);
    float va = __fdiv_rn(nv, 6.0f);

    float aa = __fmul_rn(alpha, alpha);
    float bb = __fmul_rn(beta, beta);
    float g2 = __fadd_rn(aa, bb);
    float num = __fadd_rn(__fmul_rn(bb, va), __fmul_rn(aa, va));
    float var_t = __fdiv_rn(num, __fmul_rn(g2, g2));

    float theta = atanf(__fdiv_rn(beta, alpha));
    float inv = rsqrtf(g2);
    float invs = copysignf(inv, alpha);
    float ct = alpha * invs;
    float st = beta  * invs;
    float xf = (float)h, yf = (float)w;
    float rho  = __fadd_rn(__fmul_rn(xf, ct), __fmul_rn(yf, st));
    float drho = __fadd_rn(__fmul_rn(-xf, st), __fmul_rn(yf, ct));
    float var_r = __fmul_rn(__fmul_rn(drho, drho), var_t);

    float v = mask[h * WW + w];
    bool valid = (var_t <= 100.0f) && (var_r <= 100.0f) && (v != 0.0f);

    unsigned m = __ballot_sync(0xffffffffu, valid);
    if (m) {
        int lane = threadIdx.x;
        int leader = __ffs(m) - 1;
        int base = 0;
        if (lane == leader) base = atomicAdd(&g_misc[0], __popc(m));
        base = __shfl_sync(0xffffffffu, base, leader);
        if (valid) {
            int idx = base + __popc(m & ((1u << lane) - 1u));
            float sig_t = __fsqrt_rn(__fadd_rn(var_t, 1e-12f));
            float sig_r = __fsqrt_rn(__fadd_rn(var_r, 1e-12f));
            g_pts[idx] = make_float4(theta, rho, sig_t, sig_r);
            g_val[idx] = v;
            atomicAdd(&g_misc[1 + calc_rlo(rho, sig_r)], 1);
        }
    }
}

// ---------------- scan: 360-entry prefix sum (one block) ----------------
__global__ void scan_kernel() {
    __shared__ int tmp[512];
    int t = threadIdx.x;
    tmp[t] = (t < 360) ? g_misc[1 + t] : 0;
    __syncthreads();
    for (int off = 1; off < 512; off <<= 1) {
        int v = (t >= off) ? tmp[t - off] : 0;
        __syncthreads();
        tmp[t] += v;
        __syncthreads();
    }
    if (t < 360) g_boff[t + 1] = tmp[t];
    if (t == 0)  g_boff[0] = 0;
}

// ---------------- cdf: weights, scattered into bucket order ----------------
__global__ void __launch_bounds__(256)
cdf_kernel() {
    __shared__ float tbuf[8][184];
    int lane = threadIdx.x & 31;
    int wl   = threadIdx.x >> 5;
    int warp = blockIdx.x * 8 + wl;
    int n = g_misc[0];

    for (int p = warp; p < n; p += CDF_BLOCKS * 8) {
        float4 pt = g_pts[p];
        float theta = pt.x, rho = pt.y, sig_t = pt.z, sig_r = pt.w;
        float rst = __fdiv_rn(1.0f, sig_t);
        float rsr = __fdiv_rn(1.0f, sig_r);

        // ---- rho window first (gives rlo -> destination bucket slot) ----
        float Wr = fminf(6.5f * sig_r, 62.0f);
        int rklo = max(0,   (int)ceilf ((rho - Wr - RMIN_F) / RBIN_F + 0.5f));
        int rkhi = min(360, (int)floorf((rho + Wr - RMIN_F) / RBIN_F + 0.5f));
        rklo = min(rklo, 360);
        int e = rklo + lane;
        if (e <= rkhi) {
            float ec = __fadd_rn(RMIN_F, __fmul_rn(__fsub_rn((float)e, 0.5f), RBIN_F));
            tbuf[wl][lane] = fcdf((ec - rho) * rsr);
        }
        __syncwarp();
        int lo_b = min(max(0, rklo - 1), 359);   // == calc_rlo(rho, sig_r)
        int hi_b = min(359, rkhi);
        int cnt  = min(max(hi_b - lo_b + 1, 1), 32);
        float v = g_val[p];
        float wr = 0.0f;
        int b = lo_b + lane;
        if (lane < cnt) {
            float c0 = (b     < rklo) ? 0.0f : tbuf[wl][b     - rklo];
            float c1 = (b + 1 > rkhi) ? 1.0f : tbuf[wl][b + 1 - rklo];
            wr = __fmul_rn(__fsub_rn(c1, c0), v);
        }
        int dst = 0;
        if (lane == 0) dst = g_boff[lo_b] + atomicAdd(&g_misc[361 + lo_b], 1);
        dst = __shfl_sync(0xffffffffu, dst, 0);
        g_wr[(size_t)dst * 32 + lane] = wr;
        __syncwarp();

        // ---- theta window -> dense wt[180] at dst ----
        float Wt = 6.5f * sig_t;
        int klo = max(0,   (int)ceilf ((theta - Wt - TMIN_F) / TBIN_F + 0.5f));
        int khi = min(180, (int)floorf((theta + Wt - TMIN_F) / TBIN_F + 0.5f));
        klo = min(klo, 181);
        for (int ee = klo + lane; ee <= khi; ee += 32) {
            float ec = __fadd_rn(TMIN_F, __fmul_rn(__fsub_rn((float)ee, 0.5f), TBIN_F));
            tbuf[wl][ee - klo] = fcdf((ec - theta) * rst);
        }
        __syncwarp();
        float* wtp = g_wt + (size_t)dst * 180;
        for (int j = lane; j < 180; j += 32) {
            float c0 = (j     < klo) ? 0.0f : ((j     > khi) ? 1.0f : tbuf[wl][j     - klo]);
            float c1 = (j + 1 < klo) ? 0.0f : ((j + 1 > khi) ? 1.0f : tbuf[wl][j + 1 - klo]);
            wtp[j] = __fsub_rn(c1, c0);
        }
        __syncwarp();
    }
}

// ---------------- vote: bucketed register accumulation, no hot-loop atomics ----------------
// blockIdx.x = column group (32 buckets), .y = theta tile (30 rows), .z = pixel split.
// Warp takes a bucket: lane owns column (rlo + lane); 30 rows of acc in registers.
// Per pixel-pair per row: one broadcast LDS.64 + two FFMA.
__global__ void __launch_bounds__(256)
vote_kernel(float* __restrict__ out) {
    __shared__ float  sacc[30 * 64];
    __shared__ float2 wslot[8][32];
    int tid = threadIdx.x, lane = tid & 31, warp = tid >> 5;
    int b0 = blockIdx.x * 32;
    int nb = min(32, 360 - b0);
    int tile = blockIdx.y, sp = blockIdx.z;
    int tbase = tile * 30;

    for (int i = tid; i < 30 * 64; i += 256) sacc[i] = 0.0f;
    __syncthreads();

    for (int bi = warp; bi < nb; bi += 8) {
        int b = b0 + bi;
        int s = g_boff[b], e = g_boff[b + 1];
        float acc[30];
#pragma unroll
        for (int j = 0; j < 30; j++) acc[j] = 0.0f;
        bool any = false;

        for (int p = s + sp; p < e; p += 2 * NSP) {
            int pB = p + NSP;
            bool hasB = (pB < e);
            float wrA = g_wr[(size_t)p * 32 + lane];
            float wrB = hasB ? g_wr[(size_t)pB * 32 + lane] : 0.0f;
            if (lane < 30) {
                float wa = g_wt[(size_t)p * 180 + tbase + lane];
                float wb = hasB ? g_wt[(size_t)pB * 180 + tbase + lane] : 0.0f;
                wslot[warp][lane] = make_float2(wa, wb);
            }
            __syncwarp();
            any = true;
#pragma unroll
            for (int j = 0; j < 30; j++) {
                float2 wt2 = wslot[warp][j];   // broadcast
                acc[j] = fmaf(wt2.x, wrA, acc[j]);
                acc[j] = fmaf(wt2.y, wrB, acc[j]);
            }
            __syncwarp();
        }

        if (any) {
            int c = bi + lane;                 // 0..62, in-bounds (<64)
#pragma unroll
            for (int j = 0; j < 30; j++)
                atomicAdd(&sacc[j * 64 + c], acc[j]);
        }
    }

    __syncthreads();
    // float4 global merge: cols b0..b0+63, b0 % 4 == 0 so chunks are aligned
    for (int i = tid; i < (30 * 64) / 4; i += 256) {
        int r = i >> 4, cq = (i & 15) * 4;
        int col = b0 + cq;
        if (col < 360) {
            float4 v = ((const float4*)sacc)[i];
            if (v.x != 0.0f || v.y != 0.0f || v.z != 0.0f || v.w != 0.0f)
                atomicAdd((float4*)(out + (tbase + r) * RBINS + col), v);
        }
    }
}

extern "C" void kernel_launch(void* const* d_in, const int* in_sizes, int n_in,
                              void* d_out, int out_size) {
    const float* img  = (const float*)d_in[0];
    const float* mask = (const float*)d_in[1];
    float* out = (float*)d_out;

    void* misc_ptr = nullptr;
    cudaGetSymbolAddress(&misc_ptr, g_misc);
    cudaMemsetAsync(misc_ptr, 0, sizeof(int) * 721);

    plane_kernel<<<dim3(WW / 32, HH / 8), dim3(32, 8)>>>(img, mask, out);
    scan_kernel<<<1, 512>>>();
    cdf_kernel<<<CDF_BLOCKS, 256>>>();
    vote_kernel<<<dim3(NCG, NTL, NSP), 256>>>(out);
}